// round 1
// baseline (speedup 1.0000x reference)
#include <cuda_runtime.h>
#include <math.h>

// ---------------------------------------------------------------------------
// Problem constants
// ---------------------------------------------------------------------------
#define DD        768
#define NSEQ      197
#define BTOT      18
#define BX        8          // batch rows kept
#define RREF      10
#define NHEADS    12
#define HDIM      64
#define ROWS_ALL  (BTOT*NSEQ)   // 3546
#define ROWS_X    (BX*NSEQ)     // 1576
#define ROWS_R    (RREF*NSEQ)   // 1970

// ---------------------------------------------------------------------------
// Scratch: one big device global, offsets in floats (all offsets % 4 == 0)
// ---------------------------------------------------------------------------
#define OFF_H1    0                      // 3546*192  = 680832
#define OFF_EX    680832                 // 3546*96   = 340416
#define OFF_NRM   1021248                // 3546 (pad to 3548)
#define OFF_MASK  1024796                // 1576
#define OFF_KMAT  1026372                // 1970*768  = 1512960
#define OFF_G     2539332                // 12*64*64  = 49152
#define OFF_XA    2588484                // 1576*768  = 1210368
#define OFF_QV    3798852                // 1576*1536 = 2420736
#define OFF_O     6219588                // 1576*768  = 1210368
#define OFF_TMP   7429956                // 1576*768  = 1210368
#define SCRATCH_TOTAL 8640324

__device__ float g_scratch[SCRATCH_TOTAL];

__device__ __forceinline__ float gelu_exact(float v) {
    return 0.5f * v * (1.0f + erff(v * 0.70710678118654752440f));
}

// ---------------------------------------------------------------------------
// Generic tiled fp32 GEMM: C[M,N] = A[M,K] @ B[K,N] (+bias) (+gelu)
// 128x128 block, K-tile 8, 256 threads, 8x8 per-thread register tile.
// Requires K % 8 == 0, N % 4 == 0 (true for all uses: K=768/192, N=1536/768/192).
// EPI: 0 = none, 1 = +bias, 2 = +bias then exact GELU
// ---------------------------------------------------------------------------
template <int EPI>
__global__ __launch_bounds__(256) void gemm_k(
    const float* __restrict__ A, const float* __restrict__ B,
    const float* __restrict__ bias, float* __restrict__ C,
    int M, int N, int K)
{
    __shared__ float As[8][128];
    __shared__ float Bs[8][128];

    const int tid  = threadIdx.x;
    const int row0 = blockIdx.y * 128;
    const int col0 = blockIdx.x * 128;
    const int tr   = tid >> 4;          // 0..15
    const int tc   = tid & 15;          // 0..15
    const int arow = tid >> 1;          // 0..127
    const int acol = (tid & 1) * 4;     // 0 or 4
    const int brow = tid >> 5;          // 0..7
    const int bcol = (tid & 31) * 4;    // 0..124

    float acc[8][8];
#pragma unroll
    for (int i = 0; i < 8; i++)
#pragma unroll
        for (int j = 0; j < 8; j++) acc[i][j] = 0.0f;

    for (int k0 = 0; k0 < K; k0 += 8) {
        float4 av = make_float4(0.f, 0.f, 0.f, 0.f);
        if (row0 + arow < M)
            av = *reinterpret_cast<const float4*>(A + (size_t)(row0 + arow) * K + k0 + acol);
        As[acol + 0][arow] = av.x;
        As[acol + 1][arow] = av.y;
        As[acol + 2][arow] = av.z;
        As[acol + 3][arow] = av.w;

        float4 bv = make_float4(0.f, 0.f, 0.f, 0.f);
        if (col0 + bcol < N)
            bv = *reinterpret_cast<const float4*>(B + (size_t)(k0 + brow) * N + col0 + bcol);
        *reinterpret_cast<float4*>(&Bs[brow][bcol]) = bv;

        __syncthreads();

#pragma unroll
        for (int kk = 0; kk < 8; kk++) {
            float a[8], b[8];
            *reinterpret_cast<float4*>(a)     = *reinterpret_cast<float4*>(&As[kk][tr * 8]);
            *reinterpret_cast<float4*>(a + 4) = *reinterpret_cast<float4*>(&As[kk][tr * 8 + 4]);
            *reinterpret_cast<float4*>(b)     = *reinterpret_cast<float4*>(&Bs[kk][tc * 8]);
            *reinterpret_cast<float4*>(b + 4) = *reinterpret_cast<float4*>(&Bs[kk][tc * 8 + 4]);
#pragma unroll
            for (int i = 0; i < 8; i++)
#pragma unroll
                for (int j = 0; j < 8; j++)
                    acc[i][j] += a[i] * b[j];
        }
        __syncthreads();
    }

#pragma unroll
    for (int i = 0; i < 8; i++) {
        int r = row0 + tr * 8 + i;
        if (r >= M) continue;
#pragma unroll
        for (int j = 0; j < 8; j++) {
            int c = col0 + tc * 8 + j;
            if (c >= N) continue;
            float v = acc[i][j];
            if (EPI >= 1) v += bias[c];
            if (EPI == 2) v = gelu_exact(v);
            C[(size_t)r * N + c] = v;
        }
    }
}

// ---------------------------------------------------------------------------
// Encoder stage 2 fused with row-norm: ex[s,:] = h1[s,:] @ fc2_w + fc2_b,
// nrm[s] = max(||ex[s,:]||, 1e-8).  One block (96 threads) per row.
// ---------------------------------------------------------------------------
__global__ __launch_bounds__(96) void enc2_k(
    const float* __restrict__ h1, const float* __restrict__ w2,
    const float* __restrict__ b2, float* __restrict__ ex, float* __restrict__ nrm)
{
    const int s = blockIdx.x;
    const int e = threadIdx.x;   // 0..95
    __shared__ float hs[192];
    hs[e]      = h1[(size_t)s * 192 + e];
    hs[e + 96] = h1[(size_t)s * 192 + 96 + e];
    __syncthreads();

    float acc = b2[e];
#pragma unroll 4
    for (int k = 0; k < 192; k++)
        acc += hs[k] * w2[(size_t)k * 96 + e];
    ex[(size_t)s * 96 + e] = acc;

    __shared__ float red[96];
    red[e] = acc * acc;
    __syncthreads();
    if (e < 32) {
        float t = red[e] + red[e + 32] + red[e + 64];
#pragma unroll
        for (int o = 16; o > 0; o >>= 1)
            t += __shfl_xor_sync(0xffffffffu, t, o);
        if (e == 0) nrm[s] = fmaxf(sqrtf(t), 1e-8f);
    }
}

// ---------------------------------------------------------------------------
// Mask kernel: one warp per (b,n) row.
// ---------------------------------------------------------------------------
__global__ __launch_bounds__(32) void mask_k(
    const float* __restrict__ ex, const float* __restrict__ nrm,
    float* __restrict__ mask)
{
    const int row = blockIdx.x;          // b*197 + n, < 1576
    const int n   = row % NSEQ;
    const int l   = threadIdx.x;

    const float* xv = ex + (size_t)row * 96;
    float x0 = xv[l], x1 = xv[l + 32], x2 = xv[l + 64];
    float nx = nrm[row];
    float cs = 0.0f;
#pragma unroll
    for (int r = 0; r < RREF; r++) {
        int sr = (BX + r) * NSEQ + n;
        const float* rv = ex + (size_t)sr * 96;
        float p = x0 * rv[l] + x1 * rv[l + 32] + x2 * rv[l + 64];
#pragma unroll
        for (int o = 16; o > 0; o >>= 1)
            p += __shfl_xor_sync(0xffffffffu, p, o);
        cs += p / (nx * nrm[sr]);
    }
    if (l == 0) {
        float c = (cs * 0.1f + 1.0f) * 0.5f;
        mask[row] = 0.5f + 0.5f * tanhf(25.0f * (c - 0.5f));
    }
}

// ---------------------------------------------------------------------------
// G_h = (scale^2 / R) * sum over all (r,m) rows of k[:,h*64:(h+1)*64]^T outer.
// One block per head, 256 threads, 32-row smem tiles.
// ---------------------------------------------------------------------------
__global__ __launch_bounds__(256) void gmat_k(
    const float* __restrict__ kmat, float* __restrict__ G)
{
    const int h = blockIdx.x;
    const int tid = threadIdx.x;
    __shared__ float Ks[32][64];
    const int i0 = (tid >> 4) * 4;
    const int j0 = (tid & 15) * 4;
    float acc[4][4];
#pragma unroll
    for (int i = 0; i < 4; i++)
#pragma unroll
        for (int j = 0; j < 4; j++) acc[i][j] = 0.0f;

    for (int r0 = 0; r0 < ROWS_R; r0 += 32) {
#pragma unroll
        for (int t = 0; t < 2; t++) {
            int f   = tid + t * 256;      // float4 index 0..511
            int row = f >> 4;
            int c4  = (f & 15) * 4;
            float4 v = make_float4(0.f, 0.f, 0.f, 0.f);
            if (r0 + row < ROWS_R)
                v = *reinterpret_cast<const float4*>(
                        kmat + (size_t)(r0 + row) * DD + h * 64 + c4);
            *reinterpret_cast<float4*>(&Ks[row][c4]) = v;
        }
        __syncthreads();
#pragma unroll 8
        for (int n = 0; n < 32; n++) {
            float4 a4 = *reinterpret_cast<float4*>(&Ks[n][i0]);
            float4 b4 = *reinterpret_cast<float4*>(&Ks[n][j0]);
            float a[4] = {a4.x, a4.y, a4.z, a4.w};
            float b[4] = {b4.x, b4.y, b4.z, b4.w};
#pragma unroll
            for (int i = 0; i < 4; i++)
#pragma unroll
                for (int j = 0; j < 4; j++)
                    acc[i][j] += a[i] * b[j];
        }
        __syncthreads();
    }
    const float sc = (0.125f * 0.125f) / 10.0f;   // scale^2 / R
#pragma unroll
    for (int i = 0; i < 4; i++)
#pragma unroll
        for (int j = 0; j < 4; j++)
            G[(size_t)h * 4096 + (i0 + i) * 64 + (j0 + j)] = acc[i][j] * sc;
}

// ---------------------------------------------------------------------------
// Attention core: per (b,h):  P = Q^T V (64x64), Z = G_h P, O = Q Z (197x64).
// O written at obuf[b*151296 + h*12608 + n*64 + d] which reproduces the
// reference's flat reshape exactly.
// Dynamic smem: Q(12608) V(12608) G(4096) P(4096) Z(4096) = 37504 floats.
// ---------------------------------------------------------------------------
#define ATTN_SMEM_FLOATS 37504
__global__ __launch_bounds__(256) void attn_k(
    const float* __restrict__ qv, const float* __restrict__ G,
    float* __restrict__ obuf)
{
    extern __shared__ float sm[];
    float* Qs = sm;            // 197*64
    float* Vs = sm + 12608;    // 197*64
    float* Gs = sm + 25216;    // 64*64
    float* Ps = sm + 29312;    // 64*64
    float* Zs = sm + 33408;    // 64*64

    const int b = blockIdx.x / NHEADS;
    const int h = blockIdx.x % NHEADS;
    const int tid = threadIdx.x;

    for (int i = tid; i < NSEQ * HDIM; i += 256) {
        int n = i >> 6, d = i & 63;
        size_t base = ((size_t)b * NSEQ + n) * (2 * DD) + h * 64 + d;
        Qs[i] = qv[base];
        Vs[i] = qv[base + DD];
    }
    for (int i = tid; i < 4096; i += 256)
        Gs[i] = G[(size_t)h * 4096 + i];
    __syncthreads();

    const int i0 = (tid >> 4) * 4;
    const int j0 = (tid & 15) * 4;

    // P = Q^T V
    {
        float p[4][4];
#pragma unroll
        for (int i = 0; i < 4; i++)
#pragma unroll
            for (int j = 0; j < 4; j++) p[i][j] = 0.0f;
        for (int n = 0; n < NSEQ; n++) {
            float4 qa = *reinterpret_cast<float4*>(&Qs[n * 64 + i0]);
            float4 vb = *reinterpret_cast<float4*>(&Vs[n * 64 + j0]);
            float q[4] = {qa.x, qa.y, qa.z, qa.w};
            float v[4] = {vb.x, vb.y, vb.z, vb.w};
#pragma unroll
            for (int i = 0; i < 4; i++)
#pragma unroll
                for (int j = 0; j < 4; j++)
                    p[i][j] += q[i] * v[j];
        }
#pragma unroll
        for (int i = 0; i < 4; i++)
#pragma unroll
            for (int j = 0; j < 4; j++)
                Ps[(i0 + i) * 64 + (j0 + j)] = p[i][j];
    }
    __syncthreads();

    // Z = G P
    {
        float z[4][4];
#pragma unroll
        for (int i = 0; i < 4; i++)
#pragma unroll
            for (int j = 0; j < 4; j++) z[i][j] = 0.0f;
#pragma unroll 8
        for (int k = 0; k < 64; k++) {
            float ga[4];
#pragma unroll
            for (int i = 0; i < 4; i++) ga[i] = Gs[(i0 + i) * 64 + k];
            float4 pb = *reinterpret_cast<float4*>(&Ps[k * 64 + j0]);
            float p[4] = {pb.x, pb.y, pb.z, pb.w};
#pragma unroll
            for (int i = 0; i < 4; i++)
#pragma unroll
                for (int j = 0; j < 4; j++)
                    z[i][j] += ga[i] * p[j];
        }
#pragma unroll
        for (int i = 0; i < 4; i++)
#pragma unroll
            for (int j = 0; j < 4; j++)
                Zs[(i0 + i) * 64 + (j0 + j)] = z[i][j];
    }
    __syncthreads();

    // O = Q Z  -> flat obuf (reproduces reference reshape)
    const int dj = (tid & 15) * 4;
    for (int n = tid >> 4; n < NSEQ; n += 16) {
        float o0 = 0.f, o1 = 0.f, o2 = 0.f, o3 = 0.f;
#pragma unroll 8
        for (int k = 0; k < 64; k++) {
            float q = Qs[n * 64 + k];
            float4 zz = *reinterpret_cast<float4*>(&Zs[k * 64 + dj]);
            o0 += q * zz.x; o1 += q * zz.y; o2 += q * zz.z; o3 += q * zz.w;
        }
        *reinterpret_cast<float4*>(
            &obuf[(size_t)b * (NSEQ * DD) + h * (NSEQ * HDIM) + n * 64 + dj]) =
            make_float4(o0, o1, o2, o3);
    }
}

// ---------------------------------------------------------------------------
// LayerNorm over last dim (768). One block (256 threads) per row.
// ---------------------------------------------------------------------------
__global__ __launch_bounds__(256) void ln_k(
    const float* __restrict__ in, const float* __restrict__ g,
    const float* __restrict__ beta, float* __restrict__ out)
{
    const int row = blockIdx.x;
    const int tid = threadIdx.x;
    const float* z = in + (size_t)row * DD;
    float v[3];
    float s = 0.0f;
#pragma unroll
    for (int j = 0; j < 3; j++) { v[j] = z[tid + j * 256]; s += v[j]; }

    __shared__ float red[256];
    red[tid] = s; __syncthreads();
#pragma unroll
    for (int o = 128; o > 0; o >>= 1) {
        if (tid < o) red[tid] += red[tid + o];
        __syncthreads();
    }
    float mu = red[0] * (1.0f / 768.0f);
    __syncthreads();

    float s2 = 0.0f;
#pragma unroll
    for (int j = 0; j < 3; j++) { float d = v[j] - mu; s2 += d * d; }
    red[tid] = s2; __syncthreads();
#pragma unroll
    for (int o = 128; o > 0; o >>= 1) {
        if (tid < o) red[tid] += red[tid + o];
        __syncthreads();
    }
    float rstd = rsqrtf(red[0] * (1.0f / 768.0f) + 1e-5f);

#pragma unroll
    for (int j = 0; j < 3; j++) {
        int c = tid + j * 256;
        out[(size_t)row * DD + c] = (v[j] - mu) * rstd * g[c] + beta[c];
    }
}

// ---------------------------------------------------------------------------
// Elementwise kernels
// ---------------------------------------------------------------------------
__global__ void scale_k(const float* __restrict__ x, const float* __restrict__ mask,
                        float* __restrict__ xa)
{
    int idx = blockIdx.x * blockDim.x + threadIdx.x;
    if (idx >= ROWS_X * DD) return;
    xa[idx] = x[idx] * mask[idx / DD];
}

__global__ void combine_k(const float* __restrict__ x, const float* __restrict__ xa,
                          const float* __restrict__ mask, float* __restrict__ out)
{
    int idx = blockIdx.x * blockDim.x + threadIdx.x;
    if (idx >= ROWS_ALL * DD) return;
    int row = idx / DD;
    if (row < ROWS_X) {
        float m = mask[row];
        out[idx] = m * xa[idx] + (1.0f - m) * x[idx];
    } else {
        out[idx] = x[idx];
    }
}

// ---------------------------------------------------------------------------
// Host launcher
// ---------------------------------------------------------------------------
extern "C" void kernel_launch(void* const* d_in, const int* in_sizes, int n_in,
                              void* d_out, int out_size)
{
    const float* x      = (const float*)d_in[0];
    const float* qv_w   = (const float*)d_in[1];
    const float* k_w    = (const float*)d_in[2];
    const float* proj_w = (const float*)d_in[3];
    const float* proj_b = (const float*)d_in[4];
    const float* ln_g   = (const float*)d_in[5];
    const float* ln_b   = (const float*)d_in[6];
    const float* fc1_w  = (const float*)d_in[7];
    const float* fc1_b  = (const float*)d_in[8];
    const float* fc2_w  = (const float*)d_in[9];
    const float* fc2_b  = (const float*)d_in[10];
    float* out = (float*)d_out;

    float* S = nullptr;
    cudaGetSymbolAddress((void**)&S, g_scratch);

    cudaFuncSetAttribute(attn_k, cudaFuncAttributeMaxDynamicSharedMemorySize,
                         ATTN_SMEM_FLOATS * (int)sizeof(float));

    float* h1   = S + OFF_H1;
    float* ex   = S + OFF_EX;
    float* nrm  = S + OFF_NRM;
    float* mask = S + OFF_MASK;
    float* kmat = S + OFF_KMAT;
    float* G    = S + OFF_G;
    float* xa   = S + OFF_XA;
    float* qv   = S + OFF_QV;
    float* obuf = S + OFF_O;
    float* tmp  = S + OFF_TMP;

    // 1) encoder stage 1 on all 18 batch rows: h1 = gelu(x @ fc1_w + fc1_b)
    gemm_k<2><<<dim3(2, 28), 256>>>(x, fc1_w, fc1_b, h1, ROWS_ALL, 192, DD);
    // 2) encoder stage 2 + row norms
    enc2_k<<<ROWS_ALL, 96>>>(h1, fc2_w, fc2_b, ex, nrm);
    // 3) cosine mask
    mask_k<<<ROWS_X, 32>>>(ex, nrm, mask);
    // 4) kmat = ref @ k_w
    gemm_k<0><<<dim3(6, 16), 256>>>(x + (size_t)ROWS_X * DD, k_w, nullptr, kmat,
                                    ROWS_R, DD, DD);
    // 5) per-head Gram matrices
    gmat_k<<<NHEADS, 256>>>(kmat, G);
    // 6) x0 = xm * mask
    scale_k<<<(ROWS_X * DD + 255) / 256, 256>>>(x, mask, xa);

    // 7) diffuser steps
    for (int step = 0; step < 3; step++) {
        gemm_k<0><<<dim3(12, 13), 256>>>(xa, qv_w, nullptr, qv,
                                         ROWS_X, 2 * DD, DD);
        attn_k<<<BX * NHEADS, 256, ATTN_SMEM_FLOATS * sizeof(float)>>>(qv, G, obuf);
        gemm_k<1><<<dim3(6, 13), 256>>>(obuf, proj_w, proj_b, tmp,
                                        ROWS_X, DD, DD);
        ln_k<<<ROWS_X, 256>>>(tmp, ln_g, ln_b, xa);
    }

    // 8) final combine + ref passthrough
    combine_k<<<(ROWS_ALL * DD + 255) / 256, 256>>>(x, xa, mask, out);
}

// round 4
// speedup vs baseline: 1.1031x; 1.1031x over previous
#include <cuda_runtime.h>
#include <math.h>

// ---------------------------------------------------------------------------
// Problem constants
// ---------------------------------------------------------------------------
#define DD        768
#define NSEQ      197
#define BTOT      18
#define BX        8
#define RREF      10
#define NHEADS    12
#define HDIM      64
#define ROWS_ALL  (BTOT*NSEQ)   // 3546
#define ROWS_X    (BX*NSEQ)     // 1576
#define ROWS_R    (RREF*NSEQ)   // 1970

// ---------------------------------------------------------------------------
// Scratch
// ---------------------------------------------------------------------------
#define OFF_H1    0                      // 3546*192
#define OFF_EX    680832                 // 3546*96
#define OFF_NRM   1021248                // 3546
#define OFF_MASK  1024796                // 1576
#define OFF_KMAT  1026372                // 1970*768
#define OFF_G     2539332                // 12*64*64
#define OFF_XA    2588484                // 1576*768
#define OFF_QV    3798852                // 1576*1536
#define OFF_O     6219588                // 1576*768
#define OFF_TMP   7429956                // 1576*768
#define SCRATCH_TOTAL 8640324

__device__ float g_scratch[SCRATCH_TOTAL];

__device__ __forceinline__ float gelu_exact(float v) {
    return 0.5f * v * (1.0f + erff(v * 0.70710678118654752440f));
}

// ---------------------------------------------------------------------------
// Double-buffered fp32 GEMM: C[M,N] = A[M,K] @ B[K,N] (+bias)(+gelu)
// BN=128, BK=16, 256 threads (16x16), per-thread TM x 8 register tile.
// BM=128 -> TM=8 (LA=2 float4 A-loads/thread), BM=64 -> TM=4 (LA=1).
// Requires K % 16 == 0 (768, 192 both OK).
// EPI: 0 none, 1 +bias, 2 +bias then exact GELU
// ---------------------------------------------------------------------------
template <int BM, int TM, int EPI>
__global__ __launch_bounds__(256, 2) void gemm_k(
    const float* __restrict__ A, const float* __restrict__ B,
    const float* __restrict__ bias, float* __restrict__ C,
    int M, int N, int K)
{
    constexpr int BN = 128;
    constexpr int BK = 16;
    constexpr int LA = (BM * BK) / (4 * 256);   // float4 per thread for A

    __shared__ float As[2][BK][BM + 4];
    __shared__ float Bs[2][BK][BN + 4];

    const int tid  = threadIdx.x;
    const int row0 = blockIdx.y * BM;
    const int col0 = blockIdx.x * BN;
    const int tr   = tid >> 4;   // 0..15
    const int tc   = tid & 15;   // 0..15

    float4 aR[LA];
    float4 bR[2];

    auto loadA = [&](int k0) {
#pragma unroll
        for (int i = 0; i < LA; i++) {
            int f = tid + i * 256;
            int r = f >> 2;
            int c = (f & 3) * 4;
            aR[i] = (row0 + r < M)
                ? *reinterpret_cast<const float4*>(A + (size_t)(row0 + r) * K + k0 + c)
                : make_float4(0.f, 0.f, 0.f, 0.f);
        }
    };
    auto loadB = [&](int k0) {
#pragma unroll
        for (int i = 0; i < 2; i++) {
            int f = tid + i * 256;
            int r = f >> 5;
            int c = (f & 31) * 4;
            bR[i] = (col0 + c < N)
                ? *reinterpret_cast<const float4*>(B + (size_t)(k0 + r) * N + col0 + c)
                : make_float4(0.f, 0.f, 0.f, 0.f);
        }
    };
    auto storeA = [&](int buf) {
#pragma unroll
        for (int i = 0; i < LA; i++) {
            int f = tid + i * 256;
            int r = f >> 2;
            int c = (f & 3) * 4;
            As[buf][c + 0][r] = aR[i].x;
            As[buf][c + 1][r] = aR[i].y;
            As[buf][c + 2][r] = aR[i].z;
            As[buf][c + 3][r] = aR[i].w;
        }
    };
    auto storeB = [&](int buf) {
#pragma unroll
        for (int i = 0; i < 2; i++) {
            int f = tid + i * 256;
            int r = f >> 5;
            int c = (f & 31) * 4;
            *reinterpret_cast<float4*>(&Bs[buf][r][c]) = bR[i];
        }
    };

    float acc[TM][8];
#pragma unroll
    for (int i = 0; i < TM; i++)
#pragma unroll
        for (int j = 0; j < 8; j++) acc[i][j] = 0.0f;

    loadA(0); loadB(0);
    storeA(0); storeB(0);
    __syncthreads();

    const int NT = K / BK;
    for (int t = 0; t < NT; t++) {
        const int cur = t & 1;
        const int nxt = cur ^ 1;
        if (t + 1 < NT) { loadA((t + 1) * BK); loadB((t + 1) * BK); }

#pragma unroll
        for (int kk = 0; kk < BK; kk++) {
            float a[TM], b[8];
#pragma unroll
            for (int i = 0; i < TM; i += 4)
                *reinterpret_cast<float4*>(&a[i]) =
                    *reinterpret_cast<float4*>(&As[cur][kk][tr * TM + i]);
            *reinterpret_cast<float4*>(&b[0]) =
                *reinterpret_cast<float4*>(&Bs[cur][kk][tc * 8]);
            *reinterpret_cast<float4*>(&b[4]) =
                *reinterpret_cast<float4*>(&Bs[cur][kk][tc * 8 + 4]);
#pragma unroll
            for (int i = 0; i < TM; i++)
#pragma unroll
                for (int j = 0; j < 8; j++)
                    acc[i][j] += a[i] * b[j];
        }

        if (t + 1 < NT) { storeA(nxt); storeB(nxt); }
        __syncthreads();
    }

#pragma unroll
    for (int i = 0; i < TM; i++) {
        int r = row0 + tr * TM + i;
        if (r >= M) continue;
#pragma unroll
        for (int j = 0; j < 8; j++) {
            int c = col0 + tc * 8 + j;
            if (c >= N) continue;
            float v = acc[i][j];
            if (EPI >= 1) v += bias[c];
            if (EPI == 2) v = gelu_exact(v);
            C[(size_t)r * N + c] = v;
        }
    }
}

// ---------------------------------------------------------------------------
// Row norms of ex (rows x 96): one warp per row, 4 warps per block.
// ---------------------------------------------------------------------------
__global__ __launch_bounds__(128) void norm_k(
    const float* __restrict__ ex, float* __restrict__ nrm, int rows)
{
    const int row = blockIdx.x * 4 + (threadIdx.x >> 5);
    const int l   = threadIdx.x & 31;
    if (row >= rows) return;
    const float* v = ex + (size_t)row * 96;
    float a = v[l], b = v[l + 32], c = v[l + 64];
    float s = a * a + b * b + c * c;
#pragma unroll
    for (int o = 16; o > 0; o >>= 1)
        s += __shfl_xor_sync(0xffffffffu, s, o);
    if (l == 0) nrm[row] = fmaxf(sqrtf(s), 1e-8f);
}

// ---------------------------------------------------------------------------
// Mask kernel: one warp per (b,n) row.
// ---------------------------------------------------------------------------
__global__ __launch_bounds__(32) void mask_k(
    const float* __restrict__ ex, const float* __restrict__ nrm,
    float* __restrict__ mask)
{
    const int row = blockIdx.x;
    const int n   = row % NSEQ;
    const int l   = threadIdx.x;

    const float* xv = ex + (size_t)row * 96;
    float x0 = xv[l], x1 = xv[l + 32], x2 = xv[l + 64];
    float nx = nrm[row];
    float cs = 0.0f;
#pragma unroll
    for (int r = 0; r < RREF; r++) {
        int sr = (BX + r) * NSEQ + n;
        const float* rv = ex + (size_t)sr * 96;
        float p = x0 * rv[l] + x1 * rv[l + 32] + x2 * rv[l + 64];
#pragma unroll
        for (int o = 16; o > 0; o >>= 1)
            p += __shfl_xor_sync(0xffffffffu, p, o);
        cs += p / (nx * nrm[sr]);
    }
    if (l == 0) {
        float c = (cs * 0.1f + 1.0f) * 0.5f;
        mask[row] = 0.5f + 0.5f * tanhf(25.0f * (c - 0.5f));
    }
}

// ---------------------------------------------------------------------------
// Per-head Gram matrices G_h = (scale^2/R) * K_h^T K_h over all 1970 rows.
// ---------------------------------------------------------------------------
__global__ __launch_bounds__(256) void gmat_k(
    const float* __restrict__ kmat, float* __restrict__ G)
{
    const int h = blockIdx.x;
    const int tid = threadIdx.x;
    __shared__ float Ks[32][64];
    const int i0 = (tid >> 4) * 4;
    const int j0 = (tid & 15) * 4;
    float acc[4][4];
#pragma unroll
    for (int i = 0; i < 4; i++)
#pragma unroll
        for (int j = 0; j < 4; j++) acc[i][j] = 0.0f;

    for (int r0 = 0; r0 < ROWS_R; r0 += 32) {
#pragma unroll
        for (int t = 0; t < 2; t++) {
            int f   = tid + t * 256;
            int row = f >> 4;
            int c4  = (f & 15) * 4;
            float4 v = make_float4(0.f, 0.f, 0.f, 0.f);
            if (r0 + row < ROWS_R)
                v = *reinterpret_cast<const float4*>(
                        kmat + (size_t)(r0 + row) * DD + h * 64 + c4);
            *reinterpret_cast<float4*>(&Ks[row][c4]) = v;
        }
        __syncthreads();
#pragma unroll 8
        for (int n = 0; n < 32; n++) {
            float4 a4 = *reinterpret_cast<float4*>(&Ks[n][i0]);
            float4 b4 = *reinterpret_cast<float4*>(&Ks[n][j0]);
            float a[4] = {a4.x, a4.y, a4.z, a4.w};
            float b[4] = {b4.x, b4.y, b4.z, b4.w};
#pragma unroll
            for (int i = 0; i < 4; i++)
#pragma unroll
                for (int j = 0; j < 4; j++)
                    acc[i][j] += a[i] * b[j];
        }
        __syncthreads();
    }
    const float sc = (0.125f * 0.125f) / 10.0f;
#pragma unroll
    for (int i = 0; i < 4; i++)
#pragma unroll
        for (int j = 0; j < 4; j++)
            G[(size_t)h * 4096 + (i0 + i) * 64 + (j0 + j)] = acc[i][j] * sc;
}

// ---------------------------------------------------------------------------
// Attention core: per (b,h): P = Q^T V, Z = G_h P, O = Q Z.
// ---------------------------------------------------------------------------
#define ATTN_SMEM_FLOATS 37504
__global__ __launch_bounds__(256) void attn_k(
    const float* __restrict__ qv, const float* __restrict__ G,
    float* __restrict__ obuf)
{
    extern __shared__ float sm[];
    float* Qs = sm;            // 197*64
    float* Vs = sm + 12608;    // 197*64
    float* Gs = sm + 25216;    // 64*64
    float* Ps = sm + 29312;    // 64*64
    float* Zs = sm + 33408;    // 64*64

    const int b = blockIdx.x / NHEADS;
    const int h = blockIdx.x % NHEADS;
    const int tid = threadIdx.x;

    for (int i = tid; i < NSEQ * HDIM; i += 256) {
        int n = i >> 6, d = i & 63;
        size_t base = ((size_t)b * NSEQ + n) * (2 * DD) + h * 64 + d;
        Qs[i] = qv[base];
        Vs[i] = qv[base + DD];
    }
    for (int i = tid; i < 4096; i += 256)
        Gs[i] = G[(size_t)h * 4096 + i];
    __syncthreads();

    const int i0 = (tid >> 4) * 4;
    const int j0 = (tid & 15) * 4;

    // P = Q^T V
    {
        float p[4][4];
#pragma unroll
        for (int i = 0; i < 4; i++)
#pragma unroll
            for (int j = 0; j < 4; j++) p[i][j] = 0.0f;
        for (int n = 0; n < NSEQ; n++) {
            float4 qa = *reinterpret_cast<float4*>(&Qs[n * 64 + i0]);
            float4 vb = *reinterpret_cast<float4*>(&Vs[n * 64 + j0]);
            float q[4] = {qa.x, qa.y, qa.z, qa.w};
            float v[4] = {vb.x, vb.y, vb.z, vb.w};
#pragma unroll
            for (int i = 0; i < 4; i++)
#pragma unroll
                for (int j = 0; j < 4; j++)
                    p[i][j] += q[i] * v[j];
        }
#pragma unroll
        for (int i = 0; i < 4; i++)
#pragma unroll
            for (int j = 0; j < 4; j++)
                Ps[(i0 + i) * 64 + (j0 + j)] = p[i][j];
    }
    __syncthreads();

    // Z = G P
    {
        float z[4][4];
#pragma unroll
        for (int i = 0; i < 4; i++)
#pragma unroll
            for (int j = 0; j < 4; j++) z[i][j] = 0.0f;
#pragma unroll 8
        for (int k = 0; k < 64; k++) {
            float ga[4];
#pragma unroll
            for (int i = 0; i < 4; i++) ga[i] = Gs[(i0 + i) * 64 + k];
            float4 pb = *reinterpret_cast<float4*>(&Ps[k * 64 + j0]);
            float p[4] = {pb.x, pb.y, pb.z, pb.w};
#pragma unroll
            for (int i = 0; i < 4; i++)
#pragma unroll
                for (int j = 0; j < 4; j++)
                    z[i][j] += ga[i] * p[j];
        }
#pragma unroll
        for (int i = 0; i < 4; i++)
#pragma unroll
            for (int j = 0; j < 4; j++)
                Zs[(i0 + i) * 64 + (j0 + j)] = z[i][j];
    }
    __syncthreads();

    // O = Q Z
    const int dj = (tid & 15) * 4;
    for (int n = tid >> 4; n < NSEQ; n += 16) {
        float o0 = 0.f, o1 = 0.f, o2 = 0.f, o3 = 0.f;
#pragma unroll 8
        for (int k = 0; k < 64; k++) {
            float q = Qs[n * 64 + k];
            float4 zz = *reinterpret_cast<float4*>(&Zs[k * 64 + dj]);
            o0 += q * zz.x; o1 += q * zz.y; o2 += q * zz.z; o3 += q * zz.w;
        }
        *reinterpret_cast<float4*>(
            &obuf[(size_t)b * (NSEQ * DD) + h * (NSEQ * HDIM) + n * 64 + dj]) =
            make_float4(o0, o1, o2, o3);
    }
}

// ---------------------------------------------------------------------------
// LayerNorm over last dim (768). One block (256 threads) per row.
// ---------------------------------------------------------------------------
__global__ __launch_bounds__(256) void ln_k(
    const float* __restrict__ in, const float* __restrict__ g,
    const float* __restrict__ beta, float* __restrict__ out)
{
    const int row = blockIdx.x;
    const int tid = threadIdx.x;
    const float* z = in + (size_t)row * DD;
    float v[3];
    float s = 0.0f;
#pragma unroll
    for (int j = 0; j < 3; j++) { v[j] = z[tid + j * 256]; s += v[j]; }

    __shared__ float red[256];
    red[tid] = s; __syncthreads();
#pragma unroll
    for (int o = 128; o > 0; o >>= 1) {
        if (tid < o) red[tid] += red[tid + o];
        __syncthreads();
    }
    float mu = red[0] * (1.0f / 768.0f);
    __syncthreads();

    float s2 = 0.0f;
#pragma unroll
    for (int j = 0; j < 3; j++) { float d = v[j] - mu; s2 += d * d; }
    red[tid] = s2; __syncthreads();
#pragma unroll
    for (int o = 128; o > 0; o >>= 1) {
        if (tid < o) red[tid] += red[tid + o];
        __syncthreads();
    }
    float rstd = rsqrtf(red[0] * (1.0f / 768.0f) + 1e-5f);

#pragma unroll
    for (int j = 0; j < 3; j++) {
        int c = tid + j * 256;
        out[(size_t)row * DD + c] = (v[j] - mu) * rstd * g[c] + beta[c];
    }
}

// ---------------------------------------------------------------------------
// Elementwise kernels
// ---------------------------------------------------------------------------
__global__ void scale_k(const float* __restrict__ x, const float* __restrict__ mask,
                        float* __restrict__ xa)
{
    int idx = blockIdx.x * blockDim.x + threadIdx.x;
    if (idx >= ROWS_X * DD) return;
    xa[idx] = x[idx] * mask[idx / DD];
}

__global__ void combine_k(const float* __restrict__ x, const float* __restrict__ xa,
                          const float* __restrict__ mask, float* __restrict__ out)
{
    int idx = blockIdx.x * blockDim.x + threadIdx.x;
    if (idx >= ROWS_ALL * DD) return;
    int row = idx / DD;
    if (row < ROWS_X) {
        float m = mask[row];
        out[idx] = m * xa[idx] + (1.0f - m) * x[idx];
    } else {
        out[idx] = x[idx];
    }
}

// ---------------------------------------------------------------------------
// Host launcher
// ---------------------------------------------------------------------------
extern "C" void kernel_launch(void* const* d_in, const int* in_sizes, int n_in,
                              void* d_out, int out_size)
{
    const float* x      = (const float*)d_in[0];
    const float* qv_w   = (const float*)d_in[1];
    const float* k_w    = (const float*)d_in[2];
    const float* proj_w = (const float*)d_in[3];
    const float* proj_b = (const float*)d_in[4];
    const float* ln_g   = (const float*)d_in[5];
    const float* ln_b   = (const float*)d_in[6];
    const float* fc1_w  = (const float*)d_in[7];
    const float* fc1_b  = (const float*)d_in[8];
    const float* fc2_w  = (const float*)d_in[9];
    const float* fc2_b  = (const float*)d_in[10];
    float* out = (float*)d_out;

    float* S = nullptr;
    cudaGetSymbolAddress((void**)&S, g_scratch);

    cudaFuncSetAttribute(attn_k, cudaFuncAttributeMaxDynamicSharedMemorySize,
                         ATTN_SMEM_FLOATS * (int)sizeof(float));

    float* h1   = S + OFF_H1;
    float* ex   = S + OFF_EX;
    float* nrm  = S + OFF_NRM;
    float* mask = S + OFF_MASK;
    float* kmat = S + OFF_KMAT;
    float* G    = S + OFF_G;
    float* xa   = S + OFF_XA;
    float* qv   = S + OFF_QV;
    float* obuf = S + OFF_O;
    float* tmp  = S + OFF_TMP;

    // 1) encoder stage 1 (all 18 batch rows): h1 = gelu(x @ fc1_w + fc1_b)
    gemm_k<64, 4, 2><<<dim3(2, 56), 256>>>(x, fc1_w, fc1_b, h1, ROWS_ALL, 192, DD);
    // 2) encoder stage 2: ex = h1 @ fc2_w + fc2_b
    gemm_k<64, 4, 1><<<dim3(1, 56), 256>>>(h1, fc2_w, fc2_b, ex, ROWS_ALL, 96, 192);
    // 3) row norms + cosine mask
    norm_k<<<(ROWS_ALL + 3) / 4, 128>>>(ex, nrm, ROWS_ALL);
    mask_k<<<ROWS_X, 32>>>(ex, nrm, mask);
    // 4) kmat = ref @ k_w
    gemm_k<64, 4, 0><<<dim3(6, 31), 256>>>(x + (size_t)ROWS_X * DD, k_w, nullptr,
                                           kmat, ROWS_R, DD, DD);
    // 5) per-head Gram matrices
    gmat_k<<<NHEADS, 256>>>(kmat, G);
    // 6) x0 = xm * mask
    scale_k<<<(ROWS_X * DD + 255) / 256, 256>>>(x, mask, xa);

    // 7) diffuser steps
    for (int step = 0; step < 3; step++) {
        gemm_k<128, 8, 0><<<dim3(12, 13), 256>>>(xa, qv_w, nullptr, qv,
                                                 ROWS_X, 2 * DD, DD);
        attn_k<<<BX * NHEADS, 256, ATTN_SMEM_FLOATS * sizeof(float)>>>(qv, G, obuf);
        gemm_k<64, 4, 1><<<dim3(6, 25), 256>>>(obuf, proj_w, proj_b, tmp,
                                               ROWS_X, DD, DD);
        ln_k<<<ROWS_X, 256>>>(tmp, ln_g, ln_b, xa);
    }

    // 8) final combine + ref passthrough
    combine_k<<<(ROWS_ALL * DD + 255) / 256, 256>>>(x, xa, mask, out);
}